// round 9
// baseline (speedup 1.0000x reference)
#include <cuda_runtime.h>
#include <cstdint>

#define NSTEPS 64
#define DD 16
#define THREADS 256
#define RPT 2
#define ROWS_PER_CTA (THREADS * RPT)            // 512 (divides 2^21 exactly)
#define WEIGHT_FLOATS (NSTEPS * DD * DD)        // 16384
#define SMEM_BYTES (WEIGHT_FLOATS * 4)          // 64 KB: W only

typedef unsigned long long u64;

// V lives in constant memory (64 KB), filled per-call with cudaMemcpyToSymbolAsync.
__constant__ float cV[WEIGHT_FLOATS];

// ---- packed f32x2 helpers (sm_103a) ----
__device__ __forceinline__ u64 pack2(float lo, float hi) {
    u64 r;
    asm("mov.b64 %0, {%1, %2};" : "=l"(r) : "f"(lo), "f"(hi));
    return r;
}
__device__ __forceinline__ void unpack2(u64 v, float& lo, float& hi) {
    asm("mov.b64 {%0, %1}, %2;" : "=f"(lo), "=f"(hi) : "l"(v));
}
__device__ __forceinline__ u64 fma2(u64 a, u64 b, u64 c) {
    u64 d;
    asm("fma.rn.f32x2 %0, %1, %2, %3;" : "=l"(d) : "l"(a), "l"(b), "l"(c));
    return d;
}
__device__ __forceinline__ u64 mul2(u64 a, u64 b) {
    u64 d;
    asm("mul.rn.f32x2 %0, %1, %2;" : "=l"(d) : "l"(a), "l"(b));
    return d;
}
__device__ __forceinline__ float rcp_fast(float x) {
    float r;
    asm("rcp.approx.ftz.f32 %0, %1;" : "=f"(r) : "f"(x));
    return r;
}
__device__ __forceinline__ float ex2_fast(float x) {
    float r;
    asm("ex2.approx.ftz.f32 %0, %1;" : "=f"(r) : "f"(x));
    return r;
}

// A&S 7.1.26 erf constants
#define ERF_P   0.3275911f
#define ERF_A1  0.254829592f
#define ERF_A2 -0.284496736f
#define ERF_A3  1.421413741f
#define ERF_A4 -1.453152027f
#define ERF_A5  1.061405429f
#define INV_SQRT2 0.70710678118654752440f
#define NEG_LOG2E -1.44269504088896340736f
#define ABS2_MASK 0x7fffffff7fffffffULL
// 0.5/64: folds the residual 1/NSTEPS scaling into GELU for free
#define HALF_INVN (0.5f / 64.0f)

// returns (gelu(x)/64, gelu(y)/64); erf via A&S 7.1.26, argument prep packed.
__device__ __forceinline__ u64 gelu2_scaled(u64 xy) {
    const u64 isq2  = pack2(INV_SQRT2, INV_SQRT2);
    const u64 one2  = pack2(1.0f, 1.0f);
    const u64 nl2e  = pack2(NEG_LOG2E, NEG_LOG2E);
    const u64 p2    = pack2(ERF_P, ERF_P);

    u64 axy = xy & ABS2_MASK;                 // |x|, |y|      (alu pipe)
    u64 z2  = mul2(axy, isq2);                // z = |x|/sqrt(2)
    u64 tin = fma2(p2, z2, one2);             // 1 + p*z
    u64 zz  = mul2(z2, z2);
    u64 ea  = mul2(zz, nl2e);                 // -log2(e)*z^2
    float ti_l, ti_h, ea_l, ea_h;
    unpack2(tin, ti_l, ti_h);
    unpack2(ea, ea_l, ea_h);
    u64 t2 = pack2(rcp_fast(ti_l), rcp_fast(ti_h));
    u64 e2 = pack2(ex2_fast(ea_l), ex2_fast(ea_h));
    // P = -(a5 t^5 + ... + a1 t) via negated coefs (packed Horner)
    u64 p = fma2(pack2(-ERF_A5, -ERF_A5), t2, pack2(-ERF_A4, -ERF_A4));
    p = fma2(p, t2, pack2(-ERF_A3, -ERF_A3));
    p = fma2(p, t2, pack2(-ERF_A2, -ERF_A2));
    p = fma2(p, t2, pack2(-ERF_A1, -ERF_A1));
    p = mul2(p, t2);
    u64 E2 = fma2(p, e2, one2);               // E = 1 - P(t)*e^{-z^2}
    u64 sc2 = pack2(HALF_INVN, HALF_INVN);
    u64 hx   = mul2(xy, sc2);                 // (0.5/64)*x
    u64 habs = hx & ABS2_MASK;                // (0.5/64)*|x|   (alu pipe)
    return fma2(habs, E2, hx);                // (x/2 + |x|/2*E)/64
}

__global__ __launch_bounds__(THREADS, 2)
void resnet_steps_kernel(const float* __restrict__ x,
                         const float* __restrict__ W,
                         float* __restrict__ out)
{
    extern __shared__ float smem[];   // [0,16384): W fp32
    const int tid = threadIdx.x;

    {
        const float4* Wg = reinterpret_cast<const float4*>(W);
        float4* sW4 = reinterpret_cast<float4*>(smem);
        for (int i = tid; i < WEIGHT_FLOATS / 4; i += THREADS)
            sW4[i] = Wg[i];
    }
    __syncthreads();

    const int base_row = blockIdx.x * ROWS_PER_CTA + tid;

    u64 h[RPT][8];
    #pragma unroll
    for (int r = 0; r < RPT; r++) {
        const float4* xr = reinterpret_cast<const float4*>(x) + (base_row + r * THREADS) * 4;
        #pragma unroll
        for (int q = 0; q < 4; q++) {
            float4 t = xr[q];
            h[r][2 * q]     = pack2(t.x, t.y);
            h[r][2 * q + 1] = pack2(t.z, t.w);
        }
    }

    const ulonglong2* sW = reinterpret_cast<const ulonglong2*>(smem);
    const ulonglong2* cVp = reinterpret_cast<const ulonglong2*>(cV);

    #pragma unroll 1
    for (int s = 0; s < NSTEPS; s++) {
        const ulonglong2* Ws = sW + s * (DD * DD / 4);    // 64 ulonglong2 per step
        const ulonglong2* Vs = cVp + s * (DD * DD / 4);

        // ---- g = h @ W_s  (W from shared memory, LDS.128 broadcast) ----
        u64 acc[RPT][8];

        // kp = 0: initialize acc with mul2 (no zero-init movs)
        {
            ulonglong2 w0 = Ws[0];
            ulonglong2 w1 = Ws[1];
            ulonglong2 w2 = Ws[2];
            ulonglong2 w3 = Ws[3];
            ulonglong2 w4 = Ws[4];
            ulonglong2 w5 = Ws[5];
            ulonglong2 w6 = Ws[6];
            ulonglong2 w7 = Ws[7];
            #pragma unroll
            for (int r = 0; r < RPT; r++) {
                float a, b;
                unpack2(h[r][0], a, b);
                const u64 ha = pack2(a, a);
                const u64 hb = pack2(b, b);
                acc[r][0] = mul2(ha, w0.x);
                acc[r][1] = mul2(ha, w0.y);
                acc[r][2] = mul2(ha, w1.x);
                acc[r][3] = mul2(ha, w1.y);
                acc[r][4] = mul2(ha, w2.x);
                acc[r][5] = mul2(ha, w2.y);
                acc[r][6] = mul2(ha, w3.x);
                acc[r][7] = mul2(ha, w3.y);
                acc[r][0] = fma2(hb, w4.x, acc[r][0]);
                acc[r][1] = fma2(hb, w4.y, acc[r][1]);
                acc[r][2] = fma2(hb, w5.x, acc[r][2]);
                acc[r][3] = fma2(hb, w5.y, acc[r][3]);
                acc[r][4] = fma2(hb, w6.x, acc[r][4]);
                acc[r][5] = fma2(hb, w6.y, acc[r][5]);
                acc[r][6] = fma2(hb, w7.x, acc[r][6]);
                acc[r][7] = fma2(hb, w7.y, acc[r][7]);
            }
        }

        #pragma unroll 1
        for (int kp = 1; kp < 8; kp++) {
            ulonglong2 w0 = Ws[kp * 8 + 0];
            ulonglong2 w1 = Ws[kp * 8 + 1];
            ulonglong2 w2 = Ws[kp * 8 + 2];
            ulonglong2 w3 = Ws[kp * 8 + 3];
            ulonglong2 w4 = Ws[kp * 8 + 4];
            ulonglong2 w5 = Ws[kp * 8 + 5];
            ulonglong2 w6 = Ws[kp * 8 + 6];
            ulonglong2 w7 = Ws[kp * 8 + 7];
            #pragma unroll
            for (int r = 0; r < RPT; r++) {
                float a, b;
                unpack2(h[r][kp], a, b);
                const u64 ha = pack2(a, a);
                const u64 hb = pack2(b, b);
                acc[r][0] = fma2(ha, w0.x, acc[r][0]);
                acc[r][1] = fma2(ha, w0.y, acc[r][1]);
                acc[r][2] = fma2(ha, w1.x, acc[r][2]);
                acc[r][3] = fma2(ha, w1.y, acc[r][3]);
                acc[r][4] = fma2(ha, w2.x, acc[r][4]);
                acc[r][5] = fma2(ha, w2.y, acc[r][5]);
                acc[r][6] = fma2(ha, w3.x, acc[r][6]);
                acc[r][7] = fma2(ha, w3.y, acc[r][7]);
                acc[r][0] = fma2(hb, w4.x, acc[r][0]);
                acc[r][1] = fma2(hb, w4.y, acc[r][1]);
                acc[r][2] = fma2(hb, w5.x, acc[r][2]);
                acc[r][3] = fma2(hb, w5.y, acc[r][3]);
                acc[r][4] = fma2(hb, w6.x, acc[r][4]);
                acc[r][5] = fma2(hb, w6.y, acc[r][5]);
                acc[r][6] = fma2(hb, w7.x, acc[r][6]);
                acc[r][7] = fma2(hb, w7.y, acc[r][7]);
            }
        }

        // ---- h += (GELU(g)/64) @ V_s  (V from constant memory, LDC.128) ----
        #pragma unroll 1
        for (int kp = 0; kp < 8; kp++) {
            ulonglong2 v0 = Vs[kp * 8 + 0];
            ulonglong2 v1 = Vs[kp * 8 + 1];
            ulonglong2 v2 = Vs[kp * 8 + 2];
            ulonglong2 v3 = Vs[kp * 8 + 3];
            ulonglong2 v4 = Vs[kp * 8 + 4];
            ulonglong2 v5 = Vs[kp * 8 + 5];
            ulonglong2 v6 = Vs[kp * 8 + 6];
            ulonglong2 v7 = Vs[kp * 8 + 7];
            #pragma unroll
            for (int r = 0; r < RPT; r++) {
                u64 g2 = gelu2_scaled(acc[r][kp]);
                float a, b;
                unpack2(g2, a, b);
                const u64 ga = pack2(a, a);
                const u64 gb = pack2(b, b);
                h[r][0] = fma2(ga, v0.x, h[r][0]);
                h[r][1] = fma2(ga, v0.y, h[r][1]);
                h[r][2] = fma2(ga, v1.x, h[r][2]);
                h[r][3] = fma2(ga, v1.y, h[r][3]);
                h[r][4] = fma2(ga, v2.x, h[r][4]);
                h[r][5] = fma2(ga, v2.y, h[r][5]);
                h[r][6] = fma2(ga, v3.x, h[r][6]);
                h[r][7] = fma2(ga, v3.y, h[r][7]);
                h[r][0] = fma2(gb, v4.x, h[r][0]);
                h[r][1] = fma2(gb, v4.y, h[r][1]);
                h[r][2] = fma2(gb, v5.x, h[r][2]);
                h[r][3] = fma2(gb, v5.y, h[r][3]);
                h[r][4] = fma2(gb, v6.x, h[r][4]);
                h[r][5] = fma2(gb, v6.y, h[r][5]);
                h[r][6] = fma2(gb, v7.x, h[r][6]);
                h[r][7] = fma2(gb, v7.y, h[r][7]);
            }
        }
    }

    #pragma unroll
    for (int r = 0; r < RPT; r++) {
        float4* orow = reinterpret_cast<float4*>(out) + (base_row + r * THREADS) * 4;
        #pragma unroll
        for (int q = 0; q < 4; q++) {
            float4 t;
            unpack2(h[r][2 * q],     t.x, t.y);
            unpack2(h[r][2 * q + 1], t.z, t.w);
            orow[q] = t;
        }
    }
}

extern "C" void kernel_launch(void* const* d_in, const int* in_sizes, int n_in,
                              void* d_out, int out_size) {
    const float* x = (const float*)d_in[0];
    const float* W = (const float*)d_in[1];
    const float* V = (const float*)d_in[2];
    float* out = (float*)d_out;

    static bool attr_set = false;
    if (!attr_set) {
        cudaFuncSetAttribute(resnet_steps_kernel,
                             cudaFuncAttributeMaxDynamicSharedMemorySize, SMEM_BYTES);
        attr_set = true;
    }

    // V -> constant memory (device-to-device, graph-capturable memcpy node)
    cudaMemcpyToSymbolAsync(cV, V, WEIGHT_FLOATS * sizeof(float), 0,
                            cudaMemcpyDeviceToDevice);

    const long long batch = (long long)in_sizes[0] / DD;   // 2^21
    const int grid = (int)(batch / ROWS_PER_CTA);          // 4096, exact
    resnet_steps_kernel<<<grid, THREADS, SMEM_BYTES>>>(x, W, out);
}